// round 16
// baseline (speedup 1.0000x reference)
#include <cuda_runtime.h>
#include <cuda_fp16.h>
#include <math.h>
#include <stdint.h>

// Problem dims (fixed)
#define D_MODEL 768
#define NH      12
#define HDIM    64
#define C_CLS   50
#define B_BATCH 4
#define T_LEN   1024
#define R_ROWS  200
#define BZ      48

// -------- fp32 scratch (explicitly aligned for vector access) --------
__device__ __align__(256) float g_wql[C_CLS * D_MODEL];
__device__ __align__(256) float g_scores[BZ * R_ROWS * T_LEN];
__device__ __align__(256) float g_w[BZ * C_CLS * T_LEN];

// -------- fp16 hi/lo split pool (offsets in halves; all 16B-multiples) --------
#define AH_H   0L
#define AH_L   3145728L
#define WKT_H  6291456L
#define WQT_H  7471104L
#define WVT_H  8650752L
#define W_PL   589824L
#define QH_    9830400L
#define QL_    9984000L
#define QLH_   10137600L
#define QLL_   10176000L
#define KPH_   10214400L
#define KPL_   13360128L
#define QPH_   16505856L
#define QPL_   16659456L
#define POOL_SZ 16813056L
__device__ __align__(256) __half g_hf[POOL_SZ];

// ============================================================
// helpers
// ============================================================
__device__ __forceinline__ void split2h(float v, __half& h, __half& l) {
    h = __float2half_rn(v);
    l = __float2half_rn(v - __half2float(h));
}

__device__ __forceinline__ void mma_f16(float* c, const uint32_t* a, const uint32_t* b) {
    asm volatile(
        "mma.sync.aligned.m16n8k16.row.col.f32.f16.f16.f32 "
        "{%0,%1,%2,%3}, {%4,%5,%6,%7}, {%8,%9}, {%0,%1,%2,%3};"
        : "+f"(c[0]), "+f"(c[1]), "+f"(c[2]), "+f"(c[3])
        : "r"(a[0]), "r"(a[1]), "r"(a[2]), "r"(a[3]), "r"(b[0]), "r"(b[1]));
}

// f16-accumulator variant (D/C in f16): used for the tiny side products.
__device__ __forceinline__ void mma_f16h(uint32_t* c, const uint32_t* a, const uint32_t* b) {
    asm volatile(
        "mma.sync.aligned.m16n8k16.row.col.f16.f16.f16.f16 "
        "{%0,%1}, {%2,%3,%4,%5}, {%6,%7}, {%0,%1};"
        : "+r"(c[0]), "+r"(c[1])
        : "r"(a[0]), "r"(a[1]), "r"(a[2]), "r"(a[3]), "r"(b[0]), "r"(b[1]));
}

__device__ __forceinline__ void ldsm_x4(uint32_t* r, uint32_t addr) {
    asm volatile(
        "ldmatrix.sync.aligned.m8n8.x4.shared.b16 {%0,%1,%2,%3}, [%4];"
        : "=r"(r[0]), "=r"(r[1]), "=r"(r[2]), "=r"(r[3]) : "r"(addr));
}

__device__ __forceinline__ uint32_t smem_u32(const void* p) {
    uint32_t a;
    asm("{ .reg .u64 t; cvta.to.shared.u64 t, %1; cvt.u32.u64 %0, t; }"
        : "=r"(a) : "l"(p));
    return a;
}
__device__ __forceinline__ void cp_async16(uint32_t dst, const void* src) {
    asm volatile("cp.async.cg.shared.global [%0], [%1], 16;" :: "r"(dst), "l"(src));
}
#define CP_COMMIT() asm volatile("cp.async.commit_group;")
#define CP_WAIT0()  asm volatile("cp.async.wait_group 0;")

// ============================================================
// fp32 -> (hi, lo) fp16 planes, all three inputs in one launch
// (also zeroes the output, which is poisoned)
// ============================================================
#define N_H  (B_BATCH * T_LEN * D_MODEL)   // 3145728
#define N_Q  (R_ROWS * D_MODEL)            // 153600
#define N_QL (C_CLS * D_MODEL)             // 38400

__global__ void __launch_bounds__(256) split_all_kernel(
    const float* __restrict__ H, const float* __restrict__ Q,
    const float* __restrict__ ql, __half* __restrict__ pool,
    float* __restrict__ out)
{
    int i = blockIdx.x * blockDim.x + threadIdx.x;
    if (i < B_BATCH * C_CLS) out[i] = 0.f;
    float v; long oh, ol; int idx;
    if (i < N_H) {
        v = H[i]; oh = AH_H; ol = AH_L; idx = i;
    } else if (i < N_H + N_Q) {
        idx = i - N_H; v = Q[idx]; oh = QH_; ol = QL_;
    } else if (i < N_H + N_Q + N_QL) {
        idx = i - N_H - N_Q; v = ql[idx]; oh = QLH_; ol = QLL_;
    } else return;
    __half h, l;
    split2h(v, h, l);
    pool[oh + idx] = h; pool[ol + idx] = l;
}

// W[k][n] fp32 -> Wt hi/lo [n][k] fp16 (z selects WK/WQ/WV)
__global__ void __launch_bounds__(256) split_transpose_kernel(
    const float* __restrict__ W0, const float* __restrict__ W1,
    const float* __restrict__ W2, __half* __restrict__ pool)
{
    __shared__ float t[32][33];
    const float* W = (blockIdx.z == 0) ? W0 : (blockIdx.z == 1) ? W1 : W2;
    const long oh = (blockIdx.z == 0) ? WKT_H : (blockIdx.z == 1) ? WQT_H : WVT_H;
    const long ol = oh + W_PL;
    const int k0 = blockIdx.y * 32, n0 = blockIdx.x * 32;
    const int tx = threadIdx.x & 31, ty = threadIdx.x >> 5;
#pragma unroll
    for (int j = 0; j < 32; j += 8)
        t[ty + j][tx] = W[(size_t)(k0 + ty + j) * D_MODEL + n0 + tx];
    __syncthreads();
#pragma unroll
    for (int j = 0; j < 32; j += 8) {
        float v = t[tx][ty + j];
        __half h, l;
        split2h(v, h, l);
        size_t idx = (size_t)(n0 + ty + j) * D_MODEL + k0 + tx;
        pool[oh + idx] = h; pool[ol + idx] = l;
    }
}

// ============================================================
// Fused projection GEMM (fp16x3, cp.async + ldmatrix):
//  z=0: kproj = tanh(H@WK+b)  -> fp16 hi/lo planes   (M=4096)
//  z=1: qproj = Q@WQ+b        -> fp16 hi/lo planes   (M=200)
//  z=2: wql   = ql@WV+b       -> fp32                (M=50)
// Block 128x64, BK=32, 256 thr = 8 warps (4m x 2n), warp tile 32x32.
// 3 blocks/SM. Single-barrier pipelined mainloop (issue-at-top).
// ============================================================
#define PSTR 40                  // halves per smem row (80B = 16B multiple)
#define A_PL (128 * PSTR)        // A plane halves
#define B_PL (64 * PSTR)         // B plane halves
#define STG_H (2 * A_PL + 2 * B_PL)
#define PROJ_SMEM (2 * STG_H * 2)       // 61440 bytes
#define NITER 24                 // 768 / 32

__global__ void __launch_bounds__(256, 3) proj_f16_kernel(
    const __half* __restrict__ pool, __half* __restrict__ poolw,
    const float* __restrict__ WKb, const float* __restrict__ WQb,
    const float* __restrict__ WVb, float* __restrict__ wqlout)
{
    const int z = blockIdx.z;
    int M; const __half *Ah, *Al, *Bh, *Bl; const float* bias;
    if (z == 0) {
        M = 4096; Ah = pool + AH_H; Al = pool + AH_L;
        Bh = pool + WKT_H; Bl = pool + WKT_H + W_PL; bias = WKb;
    } else if (z == 1) {
        if (blockIdx.y >= 2) return;
        M = R_ROWS; Ah = pool + QH_; Al = pool + QL_;
        Bh = pool + WQT_H; Bl = pool + WQT_H + W_PL; bias = WQb;
    } else {
        if (blockIdx.y >= 1) return;
        M = C_CLS; Ah = pool + QLH_; Al = pool + QLL_;
        Bh = pool + WVT_H; Bl = pool + WVT_H + W_PL; bias = WVb;
    }

    extern __shared__ __align__(16) __half psm[];
    const uint32_t sbase = smem_u32(psm);

    const int tid = threadIdx.x;
    const int warp = tid >> 5, lane = tid & 31;
    const int wm = (warp >> 1) * 32, wn = (warp & 1) * 32;
    const int bm = blockIdx.y * 128, bn = blockIdx.x * 64;
    const int lrow = lane >> 2, lcol = lane & 3;

    // ldmatrix lane-address components
    const int a_r = lane & 15, a_c = (lane >> 4) << 3;
    const int b_r = ((lane >> 4) << 3) + (lane & 7);
    const int b_c = ((lane >> 3) & 1) << 3;

    const int crow = tid >> 2, cch = (tid & 3) * 8;  // copy indices

    const __half* srcs[4] = { Ah, Al, Bh, Bl };
    auto issue = [&](int stage, int k0) {
#pragma unroll
        for (int p = 0; p < 2; p++) {
#pragma unroll
            for (int i = 0; i < 2; i++) {
                int row = crow + i * 64;
                const __half* src = srcs[p] + (size_t)(bm + row) * D_MODEL + k0 + cch;
                uint32_t dst = sbase + (stage * STG_H + p * A_PL + row * PSTR + cch) * 2;
                cp_async16(dst, src);
            }
        }
#pragma unroll
        for (int p = 2; p < 4; p++) {
            const __half* src = srcs[p] + (size_t)(bn + crow) * D_MODEL + k0 + cch;
            uint32_t dst = sbase + (stage * STG_H + 2 * A_PL + (p - 2) * B_PL + crow * PSTR + cch) * 2;
            cp_async16(dst, src);
        }
        CP_COMMIT();
    };

    float acc[2][4][4];
#pragma unroll
    for (int mi = 0; mi < 2; mi++)
#pragma unroll
        for (int ni = 0; ni < 4; ni++)
#pragma unroll
            for (int q = 0; q < 4; q++) acc[mi][ni][q] = 0.f;

    issue(0, 0);

    for (int it = 0; it < NITER; it++) {
        const int s = it & 1;
        CP_WAIT0();
        __syncthreads();   // stage s data visible; everyone done reading stage s^1

        if (it + 1 < NITER) issue(s ^ 1, (it + 1) * 32);   // overlaps with compute below

        const uint32_t ahs_u = sbase + (s * STG_H) * 2;
        const uint32_t als_u = ahs_u + A_PL * 2;
        const uint32_t bhs_u = als_u + A_PL * 2;
        const uint32_t bls_u = bhs_u + B_PL * 2;

#pragma unroll
        for (int ck = 0; ck < 2; ck++) {
            const int kk = ck * 16;
            uint32_t ah[2][4], al_[2][4];
#pragma unroll
            for (int mi = 0; mi < 2; mi++) {
                const uint32_t aoff = ((wm + mi * 16 + a_r) * PSTR + kk + a_c) * 2;
                ldsm_x4(ah[mi],  ahs_u + aoff);
                ldsm_x4(al_[mi], als_u + aoff);
            }
            uint32_t bh[4][2], bl_[4][2];
#pragma unroll
            for (int nj = 0; nj < 2; nj++) {
                const uint32_t boff = ((wn + nj * 16 + b_r) * PSTR + kk + b_c) * 2;
                uint32_t q[4];
                ldsm_x4(q, bhs_u + boff);
                bh[nj * 2][0] = q[0]; bh[nj * 2][1] = q[1];
                bh[nj * 2 + 1][0] = q[2]; bh[nj * 2 + 1][1] = q[3];
                ldsm_x4(q, bls_u + boff);
                bl_[nj * 2][0] = q[0]; bl_[nj * 2][1] = q[1];
                bl_[nj * 2 + 1][0] = q[2]; bl_[nj * 2 + 1][1] = q[3];
            }
#pragma unroll
            for (int ni = 0; ni < 4; ni++)
#pragma unroll
                for (int mi = 0; mi < 2; mi++)
                    mma_f16(acc[mi][ni], ah[mi], bh[ni]);
#pragma unroll
            for (int ni = 0; ni < 4; ni++)
#pragma unroll
                for (int mi = 0; mi < 2; mi++)
                    mma_f16(acc[mi][ni], ah[mi], bl_[ni]);
#pragma unroll
            for (int ni = 0; ni < 4; ni++)
#pragma unroll
                for (int mi = 0; mi < 2; mi++)
                    mma_f16(acc[mi][ni], al_[mi], bh[ni]);
        }
    }

    // epilogue
    const long oh = (z == 0) ? KPH_ : QPH_;
    const long ol = (z == 0) ? KPL_ : QPL_;
#pragma unroll
    for (int mi = 0; mi < 2; mi++) {
        const int row = bm + wm + mi * 16 + lrow;
#pragma unroll
        for (int ni = 0; ni < 4; ni++) {
            const int col = bn + wn + ni * 8 + lcol * 2;
            const float b0 = bias[col], b1 = bias[col + 1];
            float v0 = acc[mi][ni][0] + b0, v1 = acc[mi][ni][1] + b1;
            float v2 = acc[mi][ni][2] + b0, v3 = acc[mi][ni][3] + b1;
            if (z == 0) {
                v0 = tanhf(v0); v1 = tanhf(v1);
                v2 = tanhf(v2); v3 = tanhf(v3);
            }
            if (z <= 1) {
                if (row < M) {
                    __half h0, l0, h1, l1;
                    split2h(v0, h0, l0); split2h(v1, h1, l1);
                    *(__half2*)&poolw[oh + (size_t)row * D_MODEL + col] = __halves2half2(h0, h1);
                    *(__half2*)&poolw[ol + (size_t)row * D_MODEL + col] = __halves2half2(l0, l1);
                }
                if (row + 8 < M) {
                    __half h2, l2, h3, l3;
                    split2h(v2, h2, l2); split2h(v3, h3, l3);
                    *(__half2*)&poolw[oh + (size_t)(row + 8) * D_MODEL + col] = __halves2half2(h2, h3);
                    *(__half2*)&poolw[ol + (size_t)(row + 8) * D_MODEL + col] = __halves2half2(l2, l3);
                }
            } else {
                if (row < M)
                    *(float2*)&wqlout[(size_t)row * D_MODEL + col] = make_float2(v0, v1);
                if (row + 8 < M)
                    *(float2*)&wqlout[(size_t)(row + 8) * D_MODEL + col] = make_float2(v2, v3);
            }
        }
    }
}

// ============================================================
// Scores GEMM (fp16x3, cp.async + ldmatrix, f16 side-acc):
// per bz over 64-k slice; block 64x128, K=64 single pass,
// 8 warps (2x4), warp tile 32x32.
// ============================================================
#define SSTRH 72
#define SC_SMEM_B ((64 * SSTRH * 2 + 128 * SSTRH * 2) * 2)   // 55296

__global__ void __launch_bounds__(256) scores_f16_kernel(
    const __half* __restrict__ pool, float* __restrict__ scores)
{
    extern __shared__ __align__(16) __half ssm[];
    __half* Ahs = ssm;
    __half* Als = Ahs + 64 * SSTRH;
    __half* Bhs = Als + 64 * SSTRH;
    __half* Bls = Bhs + 128 * SSTRH;

    const int bz = blockIdx.z, b = bz / NH, zz = bz % NH;
    const __half* Aph = pool + QPH_ + zz * HDIM;
    const __half* Apl = pool + QPL_ + zz * HDIM;
    const __half* Bph = pool + KPH_ + (size_t)b * T_LEN * D_MODEL + zz * HDIM;
    const __half* Bpl = pool + KPL_ + (size_t)b * T_LEN * D_MODEL + zz * HDIM;
    float* Cb = scores + (size_t)bz * R_ROWS * T_LEN;

    const int tid = threadIdx.x;
    const int warp = tid >> 5, lane = tid & 31;
    const int wm = (warp >> 2) * 32, wn = (warp & 3) * 32;
    const int mbase = blockIdx.y * 64, nbase = blockIdx.x * 128;
    const int lrow = lane >> 2, lcol = lane & 3;

    const int a_r = lane & 15, a_c = (lane >> 4) << 3;
    const int b_r = ((lane >> 4) << 3) + (lane & 7);
    const int b_c = ((lane >> 3) & 1) << 3;

    // cp.async tile loads (L1-bypass). OOB A-rows clamped: their outputs
    // are never stored (row-guard) nor read downstream (rows >= 200).
#pragma unroll
    for (int i = 0; i < 2; i++) {
        int fl = tid + 256 * i, row = fl >> 3, ch = fl & 7;
        int srow = mbase + row; if (srow > R_ROWS - 1) srow = R_ROWS - 1;
        size_t ga = (size_t)srow * D_MODEL + ch * 8;
        cp_async16(smem_u32(&Ahs[row * SSTRH + ch * 8]), &Aph[ga]);
        cp_async16(smem_u32(&Als[row * SSTRH + ch * 8]), &Apl[ga]);
    }
#pragma unroll
    for (int i = 0; i < 4; i++) {
        int fl = tid + 256 * i, row = fl >> 3, ch = fl & 7;
        size_t gb = (size_t)(nbase + row) * D_MODEL + ch * 8;
        cp_async16(smem_u32(&Bhs[row * SSTRH + ch * 8]), &Bph[gb]);
        cp_async16(smem_u32(&Bls[row * SSTRH + ch * 8]), &Bpl[gb]);
    }
    CP_COMMIT();
    CP_WAIT0();
    __syncthreads();

    const uint32_t ahs_u = smem_u32(Ahs), als_u = smem_u32(Als);
    const uint32_t bhs_u = smem_u32(Bhs), bls_u = smem_u32(Bls);

    float acc[2][4][4];
    uint32_t sacc[2][4][2];          // f16 accumulator for side products
#pragma unroll
    for (int mi = 0; mi < 2; mi++)
#pragma unroll
        for (int ni = 0; ni < 4; ni++) {
#pragma unroll
            for (int q = 0; q < 4; q++) acc[mi][ni][q] = 0.f;
            sacc[mi][ni][0] = 0u; sacc[mi][ni][1] = 0u;
        }

#pragma unroll
    for (int ck = 0; ck < 4; ck++) {
        const int kk = ck * 16;
        uint32_t ah[2][4], al_[2][4];
#pragma unroll
        for (int mi = 0; mi < 2; mi++) {
            const uint32_t aoff = ((wm + mi * 16 + a_r) * SSTRH + kk + a_c) * 2;
            ldsm_x4(ah[mi],  ahs_u + aoff);
            ldsm_x4(al_[mi], als_u + aoff);
        }
        uint32_t bh[4][2], bl_[4][2];
#pragma unroll
        for (int nj = 0; nj < 2; nj++) {
            const uint32_t boff = ((wn + nj * 16 + b_r) * SSTRH + kk + b_c) * 2;
            uint32_t q[4];
            ldsm_x4(q, bhs_u + boff);
            bh[nj * 2][0] = q[0]; bh[nj * 2][1] = q[1];
            bh[nj * 2 + 1][0] = q[2]; bh[nj * 2 + 1][1] = q[3];
            ldsm_x4(q, bls_u + boff);
            bl_[nj * 2][0] = q[0]; bl_[nj * 2][1] = q[1];
            bl_[nj * 2 + 1][0] = q[2]; bl_[nj * 2 + 1][1] = q[3];
        }
        // main product in f32
#pragma unroll
        for (int ni = 0; ni < 4; ni++)
#pragma unroll
            for (int mi = 0; mi < 2; mi++)
                mma_f16(acc[mi][ni], ah[mi], bh[ni]);
        // side products (each ~2^-11 of main) in f16 acc
#pragma unroll
        for (int ni = 0; ni < 4; ni++)
#pragma unroll
            for (int mi = 0; mi < 2; mi++)
                mma_f16h(sacc[mi][ni], ah[mi], bl_[ni]);
#pragma unroll
        for (int ni = 0; ni < 4; ni++)
#pragma unroll
            for (int mi = 0; mi < 2; mi++)
                mma_f16h(sacc[mi][ni], al_[mi], bh[ni]);
    }

#pragma unroll
    for (int mi = 0; mi < 2; mi++) {
        const int row = mbase + wm + mi * 16 + lrow;
#pragma unroll
        for (int ni = 0; ni < 4; ni++) {
            const int col = nbase + wn + ni * 8 + lcol * 2;
            float2 s01 = __half22float2(*(__half2*)&sacc[mi][ni][0]);
            float2 s23 = __half22float2(*(__half2*)&sacc[mi][ni][1]);
            if (row < R_ROWS)
                *(float2*)&Cb[(size_t)row * T_LEN + col] =
                    make_float2(acc[mi][ni][0] + s01.x, acc[mi][ni][1] + s01.y);
            if (row + 8 < R_ROWS)
                *(float2*)&Cb[(size_t)(row + 8) * T_LEN + col] =
                    make_float2(acc[mi][ni][2] + s23.x, acc[mi][ni][3] + s23.y);
        }
    }
}

// ============================================================
// Softmax over t for 4 synonym rows -> combined mean weights
// ============================================================
__global__ void __launch_bounds__(128) softmax_combine_kernel(
    const float* __restrict__ scores, float* __restrict__ w)
{
    __shared__ float ex[4][1024];
    __shared__ float invl[4];
    const int blk = blockIdx.x;
    const int bz = blk / C_CLS, c = blk % C_CLS;
    const int warp = threadIdx.x >> 5, lane = threadIdx.x & 31;

    const float* row = scores + ((size_t)bz * R_ROWS + c * 4 + warp) * T_LEN;

    float m = -INFINITY;
    for (int t = lane; t < T_LEN; t += 32) m = fmaxf(m, row[t]);
#pragma unroll
    for (int o = 16; o > 0; o >>= 1) m = fmaxf(m, __shfl_xor_sync(0xffffffffu, m, o));

    float ssum = 0.f;
    for (int t = lane; t < T_LEN; t += 32) {
        float e = expf(row[t] - m);
        ex[warp][t] = e;
        ssum += e;
    }
#pragma unroll
    for (int o = 16; o > 0; o >>= 1) ssum += __shfl_xor_sync(0xffffffffu, ssum, o);
    if (lane == 0) invl[warp] = 0.25f / ssum;
    __syncthreads();

    float* wr = w + ((size_t)bz * C_CLS + c) * T_LEN;
    for (int t = threadIdx.x; t < T_LEN; t += 128)
        wr[t] = ex[0][t] * invl[0] + ex[1][t] * invl[1]
              + ex[2][t] * invl[2] + ex[3][t] * invl[3];
}

// ============================================================
// Fused m2 + final (smem pad 68 = 272B stride, 16B multiple)
// ============================================================
__global__ void __launch_bounds__(256) m2_fused_kernel(
    const float* __restrict__ H, const float* __restrict__ wql,
    const float* __restrict__ w, float* __restrict__ out)
{
    const int bz = blockIdx.z;
    const int b = bz / NH, z = bz % NH;
    const int tbase = blockIdx.y * 64;

    __shared__ float Qs[64][68];
    __shared__ float Ks[64][68];

    const int tid = threadIdx.x;

#pragma unroll
    for (int i = 0; i < 4; i++) {
        int fl = tid + 256 * i;
        int row = fl >> 4;
        int hc = (fl & 15) * 4;
        float4 v = *(const float4*)&H[(size_t)(b * T_LEN + tbase + row) * D_MODEL + z * HDIM + hc];
        Qs[hc + 0][row] = tanhf(v.x); Qs[hc + 1][row] = tanhf(v.y);
        Qs[hc + 2][row] = tanhf(v.z); Qs[hc + 3][row] = tanhf(v.w);
    }
#pragma unroll
    for (int i = 0; i < 4; i++) {
        int fl = tid + 256 * i;
        int row = fl >> 4;
        int hc = (fl & 15) * 4;
        float4 v = make_float4(0.f, 0.f, 0.f, 0.f);
        if (row < C_CLS)
            v = *(const float4*)&wql[(size_t)row * D_MODEL + z * HDIM + hc];
        Ks[hc + 0][row] = v.x; Ks[hc + 1][row] = v.y;
        Ks[hc + 2][row] = v.z; Ks[hc + 3][row] = v.w;
    }
    __syncthreads();

    const int tx = tid & 15, ty = tid >> 4;
    float acc[4][4];
#pragma unroll
    for (int i = 0; i < 4; i++)
#pragma unroll
        for (int j = 0; j < 4; j++) acc[i][j] = 0.f;

#pragma unroll
    for (int h = 0; h < 64; h++) {
        float ar[4], br[4];
        *(float4*)&ar[0] = *(float4*)&Qs[h][ty * 4];
        *(float4*)&br[0] = *(float4*)&Ks[h][tx * 4];
#pragma unroll
        for (int i = 0; i < 4; i++)
#pragma unroll
            for (int j = 0; j < 4; j++)
                acc[i][j] = fmaf(ar[i], br[j], acc[i][j]);
    }
    __syncthreads();

    float* pm = &Qs[0][0];
    float p[4];
#pragma unroll
    for (int j = 0; j < 4; j++) {
        const int c = tx * 4 + j;
        p[j] = 0.f;
        if (c < C_CLS) {
            float4 wv = *(const float4*)&w[((size_t)bz * C_CLS + c) * T_LEN + tbase + ty * 4];
            p[j] = acc[0][j] * wv.x + acc[1][j] * wv.y
                 + acc[2][j] * wv.z + acc[3][j] * wv.w;
        }
        pm[ty * 64 + tx * 4 + j] = p[j];
    }
    __syncthreads();

    if (tid < 64 && tid < C_CLS) {
        float s = 0.f;
#pragma unroll
        for (int r = 0; r < 16; r++) s += pm[r * 64 + tid];
        atomicAdd(&out[b * C_CLS + tid], s);
    }
}

// ============================================================
extern "C" void kernel_launch(void* const* d_in, const int* in_sizes, int n_in,
                              void* d_out, int out_size)
{
    const float* Q   = (const float*)d_in[0];
    const float* H   = (const float*)d_in[1];
    const float* ql  = (const float*)d_in[2];
    const float* WQw = (const float*)d_in[3];
    const float* WQb = (const float*)d_in[4];
    const float* WKw = (const float*)d_in[5];
    const float* WKb = (const float*)d_in[6];
    const float* WVw = (const float*)d_in[7];
    const float* WVb = (const float*)d_in[8];
    float* out = (float*)d_out;

    __half* pool;
    float *wql, *scores, *w;
    cudaGetSymbolAddress((void**)&pool,   g_hf);
    cudaGetSymbolAddress((void**)&wql,    g_wql);
    cudaGetSymbolAddress((void**)&scores, g_scores);
    cudaGetSymbolAddress((void**)&w,      g_w);

    cudaFuncSetAttribute(proj_f16_kernel,
                         cudaFuncAttributeMaxDynamicSharedMemorySize, PROJ_SMEM);
    cudaFuncSetAttribute(scores_f16_kernel,
                         cudaFuncAttributeMaxDynamicSharedMemorySize, SC_SMEM_B);

    // pre-split fp32 -> fp16 hi/lo (also zeroes out)
    split_all_kernel<<<(N_H + N_Q + N_QL + 255) / 256, 256>>>(H, Q, ql, pool, out);
    split_transpose_kernel<<<dim3(24, 24, 3), 256>>>(WKw, WQw, WVw, pool);

    // fused projections (single-barrier pipelined, 3 blocks/SM)
    proj_f16_kernel<<<dim3(12, 32, 3), 256, PROJ_SMEM>>>(pool, pool, WKb, WQb, WVb, wql);

    // scores per (b,z): cp.async loads + fp16x3 mma (f16 side-acc)
    scores_f16_kernel<<<dim3(8, 4, BZ), 256, SC_SMEM_B>>>(pool, scores);

    softmax_combine_kernel<<<BZ * C_CLS, 128>>>(scores, w);

    m2_fused_kernel<<<dim3(1, 16, BZ), 256>>>(H, wql, w, out);
}

// round 17
// speedup vs baseline: 1.0225x; 1.0225x over previous
#include <cuda_runtime.h>
#include <cuda_fp16.h>
#include <math.h>
#include <stdint.h>

// Problem dims (fixed)
#define D_MODEL 768
#define NH      12
#define HDIM    64
#define C_CLS   50
#define B_BATCH 4
#define T_LEN   1024
#define R_ROWS  200
#define BZ      48

// -------- fp32 scratch (explicitly aligned for vector access) --------
__device__ __align__(256) float g_wql[C_CLS * D_MODEL];
__device__ __align__(256) float g_scores[BZ * R_ROWS * T_LEN];
__device__ __align__(256) float g_w[BZ * C_CLS * T_LEN];

// -------- fp16 hi/lo split pool (offsets in halves; all 16B-multiples) --------
#define AH_H   0L
#define AH_L   3145728L
#define WKT_H  6291456L
#define WQT_H  7471104L
#define WVT_H  8650752L
#define W_PL   589824L
#define QH_    9830400L
#define QL_    9984000L
#define QLH_   10137600L
#define QLL_   10176000L
#define KPH_   10214400L
#define KPL_   13360128L
#define QPH_   16505856L
#define QPL_   16659456L
#define POOL_SZ 16813056L
__device__ __align__(256) __half g_hf[POOL_SZ];

// ============================================================
// helpers
// ============================================================
__device__ __forceinline__ void split2h(float v, __half& h, __half& l) {
    h = __float2half_rn(v);
    l = __float2half_rn(v - __half2float(h));
}

__device__ __forceinline__ void mma_f16(float* c, const uint32_t* a, const uint32_t* b) {
    asm volatile(
        "mma.sync.aligned.m16n8k16.row.col.f32.f16.f16.f32 "
        "{%0,%1,%2,%3}, {%4,%5,%6,%7}, {%8,%9}, {%0,%1,%2,%3};"
        : "+f"(c[0]), "+f"(c[1]), "+f"(c[2]), "+f"(c[3])
        : "r"(a[0]), "r"(a[1]), "r"(a[2]), "r"(a[3]), "r"(b[0]), "r"(b[1]));
}

__device__ __forceinline__ void ldsm_x4(uint32_t* r, uint32_t addr) {
    asm volatile(
        "ldmatrix.sync.aligned.m8n8.x4.shared.b16 {%0,%1,%2,%3}, [%4];"
        : "=r"(r[0]), "=r"(r[1]), "=r"(r[2]), "=r"(r[3]) : "r"(addr));
}

__device__ __forceinline__ uint32_t smem_u32(const void* p) {
    uint32_t a;
    asm("{ .reg .u64 t; cvta.to.shared.u64 t, %1; cvt.u32.u64 %0, t; }"
        : "=r"(a) : "l"(p));
    return a;
}
__device__ __forceinline__ void cp_async16(uint32_t dst, const void* src) {
    asm volatile("cp.async.cg.shared.global [%0], [%1], 16;" :: "r"(dst), "l"(src));
}
#define CP_COMMIT() asm volatile("cp.async.commit_group;")
#define CP_WAIT0()  asm volatile("cp.async.wait_group 0;")

// ============================================================
// fp32 -> (hi, lo) fp16 planes, all three inputs in one launch
// (also zeroes the output, which is poisoned)
// ============================================================
#define N_H  (B_BATCH * T_LEN * D_MODEL)   // 3145728
#define N_Q  (R_ROWS * D_MODEL)            // 153600
#define N_QL (C_CLS * D_MODEL)             // 38400

__global__ void __launch_bounds__(256) split_all_kernel(
    const float* __restrict__ H, const float* __restrict__ Q,
    const float* __restrict__ ql, __half* __restrict__ pool,
    float* __restrict__ out)
{
    int i = blockIdx.x * blockDim.x + threadIdx.x;
    if (i < B_BATCH * C_CLS) out[i] = 0.f;
    float v; long oh, ol; int idx;
    if (i < N_H) {
        v = H[i]; oh = AH_H; ol = AH_L; idx = i;
    } else if (i < N_H + N_Q) {
        idx = i - N_H; v = Q[idx]; oh = QH_; ol = QL_;
    } else if (i < N_H + N_Q + N_QL) {
        idx = i - N_H - N_Q; v = ql[idx]; oh = QLH_; ol = QLL_;
    } else return;
    __half h, l;
    split2h(v, h, l);
    pool[oh + idx] = h; pool[ol + idx] = l;
}

// W[k][n] fp32 -> Wt hi/lo [n][k] fp16 (z selects WK/WQ/WV)
__global__ void __launch_bounds__(256) split_transpose_kernel(
    const float* __restrict__ W0, const float* __restrict__ W1,
    const float* __restrict__ W2, __half* __restrict__ pool)
{
    __shared__ float t[32][33];
    const float* W = (blockIdx.z == 0) ? W0 : (blockIdx.z == 1) ? W1 : W2;
    const long oh = (blockIdx.z == 0) ? WKT_H : (blockIdx.z == 1) ? WQT_H : WVT_H;
    const long ol = oh + W_PL;
    const int k0 = blockIdx.y * 32, n0 = blockIdx.x * 32;
    const int tx = threadIdx.x & 31, ty = threadIdx.x >> 5;
#pragma unroll
    for (int j = 0; j < 32; j += 8)
        t[ty + j][tx] = W[(size_t)(k0 + ty + j) * D_MODEL + n0 + tx];
    __syncthreads();
#pragma unroll
    for (int j = 0; j < 32; j += 8) {
        float v = t[tx][ty + j];
        __half h, l;
        split2h(v, h, l);
        size_t idx = (size_t)(n0 + ty + j) * D_MODEL + k0 + tx;
        pool[oh + idx] = h; pool[ol + idx] = l;
    }
}

// ============================================================
// Fused projection GEMM (fp16x3, cp.async + ldmatrix):
//  z=0: kproj = tanh(H@WK+b)  -> fp16 hi/lo planes   (M=4096)
//  z=1: qproj = Q@WQ+b        -> fp16 hi/lo planes   (M=200)
//  z=2: wql   = ql@WV+b       -> fp32                (M=50)
// Block 128x64, BK=32, 256 thr = 8 warps (4m x 2n), warp tile 32x32.
// 3 blocks/SM. Single-barrier pipelined mainloop (issue-at-top).
// ============================================================
#define PSTR 40                  // halves per smem row (80B = 16B multiple)
#define A_PL (128 * PSTR)        // A plane halves
#define B_PL (64 * PSTR)         // B plane halves
#define STG_H (2 * A_PL + 2 * B_PL)
#define PROJ_SMEM (2 * STG_H * 2)       // 61440 bytes
#define NITER 24                 // 768 / 32

__global__ void __launch_bounds__(256, 3) proj_f16_kernel(
    const __half* __restrict__ pool, __half* __restrict__ poolw,
    const float* __restrict__ WKb, const float* __restrict__ WQb,
    const float* __restrict__ WVb, float* __restrict__ wqlout)
{
    const int z = blockIdx.z;
    int M; const __half *Ah, *Al, *Bh, *Bl; const float* bias;
    if (z == 0) {
        M = 4096; Ah = pool + AH_H; Al = pool + AH_L;
        Bh = pool + WKT_H; Bl = pool + WKT_H + W_PL; bias = WKb;
    } else if (z == 1) {
        if (blockIdx.y >= 2) return;
        M = R_ROWS; Ah = pool + QH_; Al = pool + QL_;
        Bh = pool + WQT_H; Bl = pool + WQT_H + W_PL; bias = WQb;
    } else {
        if (blockIdx.y >= 1) return;
        M = C_CLS; Ah = pool + QLH_; Al = pool + QLL_;
        Bh = pool + WVT_H; Bl = pool + WVT_H + W_PL; bias = WVb;
    }

    extern __shared__ __align__(16) __half psm[];
    const uint32_t sbase = smem_u32(psm);

    const int tid = threadIdx.x;
    const int warp = tid >> 5, lane = tid & 31;
    const int wm = (warp >> 1) * 32, wn = (warp & 1) * 32;
    const int bm = blockIdx.y * 128, bn = blockIdx.x * 64;
    const int lrow = lane >> 2, lcol = lane & 3;

    // ldmatrix lane-address components
    const int a_r = lane & 15, a_c = (lane >> 4) << 3;
    const int b_r = ((lane >> 4) << 3) + (lane & 7);
    const int b_c = ((lane >> 3) & 1) << 3;

    const int crow = tid >> 2, cch = (tid & 3) * 8;  // copy indices

    const __half* srcs[4] = { Ah, Al, Bh, Bl };
    auto issue = [&](int stage, int k0) {
#pragma unroll
        for (int p = 0; p < 2; p++) {
#pragma unroll
            for (int i = 0; i < 2; i++) {
                int row = crow + i * 64;
                const __half* src = srcs[p] + (size_t)(bm + row) * D_MODEL + k0 + cch;
                uint32_t dst = sbase + (stage * STG_H + p * A_PL + row * PSTR + cch) * 2;
                cp_async16(dst, src);
            }
        }
#pragma unroll
        for (int p = 2; p < 4; p++) {
            const __half* src = srcs[p] + (size_t)(bn + crow) * D_MODEL + k0 + cch;
            uint32_t dst = sbase + (stage * STG_H + 2 * A_PL + (p - 2) * B_PL + crow * PSTR + cch) * 2;
            cp_async16(dst, src);
        }
        CP_COMMIT();
    };

    float acc[2][4][4];
#pragma unroll
    for (int mi = 0; mi < 2; mi++)
#pragma unroll
        for (int ni = 0; ni < 4; ni++)
#pragma unroll
            for (int q = 0; q < 4; q++) acc[mi][ni][q] = 0.f;

    issue(0, 0);

    for (int it = 0; it < NITER; it++) {
        const int s = it & 1;
        CP_WAIT0();
        __syncthreads();   // stage s data visible; everyone done reading stage s^1

        if (it + 1 < NITER) issue(s ^ 1, (it + 1) * 32);   // overlaps with compute below

        const uint32_t ahs_u = sbase + (s * STG_H) * 2;
        const uint32_t als_u = ahs_u + A_PL * 2;
        const uint32_t bhs_u = als_u + A_PL * 2;
        const uint32_t bls_u = bhs_u + B_PL * 2;

#pragma unroll
        for (int ck = 0; ck < 2; ck++) {
            const int kk = ck * 16;
            uint32_t ah[2][4], al_[2][4];
#pragma unroll
            for (int mi = 0; mi < 2; mi++) {
                const uint32_t aoff = ((wm + mi * 16 + a_r) * PSTR + kk + a_c) * 2;
                ldsm_x4(ah[mi],  ahs_u + aoff);
                ldsm_x4(al_[mi], als_u + aoff);
            }
            uint32_t bh[4][2], bl_[4][2];
#pragma unroll
            for (int nj = 0; nj < 2; nj++) {
                const uint32_t boff = ((wn + nj * 16 + b_r) * PSTR + kk + b_c) * 2;
                uint32_t q[4];
                ldsm_x4(q, bhs_u + boff);
                bh[nj * 2][0] = q[0]; bh[nj * 2][1] = q[1];
                bh[nj * 2 + 1][0] = q[2]; bh[nj * 2 + 1][1] = q[3];
                ldsm_x4(q, bls_u + boff);
                bl_[nj * 2][0] = q[0]; bl_[nj * 2][1] = q[1];
                bl_[nj * 2 + 1][0] = q[2]; bl_[nj * 2 + 1][1] = q[3];
            }
#pragma unroll
            for (int ni = 0; ni < 4; ni++)
#pragma unroll
                for (int mi = 0; mi < 2; mi++)
                    mma_f16(acc[mi][ni], ah[mi], bh[ni]);
#pragma unroll
            for (int ni = 0; ni < 4; ni++)
#pragma unroll
                for (int mi = 0; mi < 2; mi++)
                    mma_f16(acc[mi][ni], ah[mi], bl_[ni]);
#pragma unroll
            for (int ni = 0; ni < 4; ni++)
#pragma unroll
                for (int mi = 0; mi < 2; mi++)
                    mma_f16(acc[mi][ni], al_[mi], bh[ni]);
        }
    }

    // epilogue
    const long oh = (z == 0) ? KPH_ : QPH_;
    const long ol = (z == 0) ? KPL_ : QPL_;
#pragma unroll
    for (int mi = 0; mi < 2; mi++) {
        const int row = bm + wm + mi * 16 + lrow;
#pragma unroll
        for (int ni = 0; ni < 4; ni++) {
            const int col = bn + wn + ni * 8 + lcol * 2;
            const float b0 = bias[col], b1 = bias[col + 1];
            float v0 = acc[mi][ni][0] + b0, v1 = acc[mi][ni][1] + b1;
            float v2 = acc[mi][ni][2] + b0, v3 = acc[mi][ni][3] + b1;
            if (z == 0) {
                v0 = tanhf(v0); v1 = tanhf(v1);
                v2 = tanhf(v2); v3 = tanhf(v3);
            }
            if (z <= 1) {
                if (row < M) {
                    __half h0, l0, h1, l1;
                    split2h(v0, h0, l0); split2h(v1, h1, l1);
                    *(__half2*)&poolw[oh + (size_t)row * D_MODEL + col] = __halves2half2(h0, h1);
                    *(__half2*)&poolw[ol + (size_t)row * D_MODEL + col] = __halves2half2(l0, l1);
                }
                if (row + 8 < M) {
                    __half h2, l2, h3, l3;
                    split2h(v2, h2, l2); split2h(v3, h3, l3);
                    *(__half2*)&poolw[oh + (size_t)(row + 8) * D_MODEL + col] = __halves2half2(h2, h3);
                    *(__half2*)&poolw[ol + (size_t)(row + 8) * D_MODEL + col] = __halves2half2(l2, l3);
                }
            } else {
                if (row < M)
                    *(float2*)&wqlout[(size_t)row * D_MODEL + col] = make_float2(v0, v1);
                if (row + 8 < M)
                    *(float2*)&wqlout[(size_t)(row + 8) * D_MODEL + col] = make_float2(v2, v3);
            }
        }
    }
}

// ============================================================
// Scores GEMM (fp16x3, cp.async + ldmatrix, f32 acc):
// per bz over 64-k slice; block 64x128, K=64 single pass,
// 8 warps (2x4), warp tile 32x32. Target 4 blocks/SM.
// ============================================================
#define SSTRH 72
#define SC_SMEM_B ((64 * SSTRH * 2 + 128 * SSTRH * 2) * 2)   // 55296

__global__ void __launch_bounds__(256, 4) scores_f16_kernel(
    const __half* __restrict__ pool, float* __restrict__ scores)
{
    extern __shared__ __align__(16) __half ssm[];
    __half* Ahs = ssm;
    __half* Als = Ahs + 64 * SSTRH;
    __half* Bhs = Als + 64 * SSTRH;
    __half* Bls = Bhs + 128 * SSTRH;

    const int bz = blockIdx.z, b = bz / NH, zz = bz % NH;
    const __half* Aph = pool + QPH_ + zz * HDIM;
    const __half* Apl = pool + QPL_ + zz * HDIM;
    const __half* Bph = pool + KPH_ + (size_t)b * T_LEN * D_MODEL + zz * HDIM;
    const __half* Bpl = pool + KPL_ + (size_t)b * T_LEN * D_MODEL + zz * HDIM;
    float* Cb = scores + (size_t)bz * R_ROWS * T_LEN;

    const int tid = threadIdx.x;
    const int warp = tid >> 5, lane = tid & 31;
    const int wm = (warp >> 2) * 32, wn = (warp & 3) * 32;
    const int mbase = blockIdx.y * 64, nbase = blockIdx.x * 128;
    const int lrow = lane >> 2, lcol = lane & 3;

    const int a_r = lane & 15, a_c = (lane >> 4) << 3;
    const int b_r = ((lane >> 4) << 3) + (lane & 7);
    const int b_c = ((lane >> 3) & 1) << 3;

    // cp.async tile loads (L1-bypass). OOB A-rows clamped: their outputs
    // are never stored (row-guard) nor read downstream (rows >= 200).
#pragma unroll
    for (int i = 0; i < 2; i++) {
        int fl = tid + 256 * i, row = fl >> 3, ch = fl & 7;
        int srow = mbase + row; if (srow > R_ROWS - 1) srow = R_ROWS - 1;
        size_t ga = (size_t)srow * D_MODEL + ch * 8;
        cp_async16(smem_u32(&Ahs[row * SSTRH + ch * 8]), &Aph[ga]);
        cp_async16(smem_u32(&Als[row * SSTRH + ch * 8]), &Apl[ga]);
    }
#pragma unroll
    for (int i = 0; i < 4; i++) {
        int fl = tid + 256 * i, row = fl >> 3, ch = fl & 7;
        size_t gb = (size_t)(nbase + row) * D_MODEL + ch * 8;
        cp_async16(smem_u32(&Bhs[row * SSTRH + ch * 8]), &Bph[gb]);
        cp_async16(smem_u32(&Bls[row * SSTRH + ch * 8]), &Bpl[gb]);
    }
    CP_COMMIT();
    CP_WAIT0();
    __syncthreads();

    const uint32_t ahs_u = smem_u32(Ahs), als_u = smem_u32(Als);
    const uint32_t bhs_u = smem_u32(Bhs), bls_u = smem_u32(Bls);

    float acc[2][4][4];
#pragma unroll
    for (int mi = 0; mi < 2; mi++)
#pragma unroll
        for (int ni = 0; ni < 4; ni++)
#pragma unroll
            for (int q = 0; q < 4; q++) acc[mi][ni][q] = 0.f;

#pragma unroll
    for (int ck = 0; ck < 4; ck++) {
        const int kk = ck * 16;
        uint32_t ah[2][4], al_[2][4];
#pragma unroll
        for (int mi = 0; mi < 2; mi++) {
            const uint32_t aoff = ((wm + mi * 16 + a_r) * SSTRH + kk + a_c) * 2;
            ldsm_x4(ah[mi],  ahs_u + aoff);
            ldsm_x4(al_[mi], als_u + aoff);
        }
        uint32_t bh[4][2], bl_[4][2];
#pragma unroll
        for (int nj = 0; nj < 2; nj++) {
            const uint32_t boff = ((wn + nj * 16 + b_r) * SSTRH + kk + b_c) * 2;
            uint32_t q[4];
            ldsm_x4(q, bhs_u + boff);
            bh[nj * 2][0] = q[0]; bh[nj * 2][1] = q[1];
            bh[nj * 2 + 1][0] = q[2]; bh[nj * 2 + 1][1] = q[3];
            ldsm_x4(q, bls_u + boff);
            bl_[nj * 2][0] = q[0]; bl_[nj * 2][1] = q[1];
            bl_[nj * 2 + 1][0] = q[2]; bl_[nj * 2 + 1][1] = q[3];
        }
#pragma unroll
        for (int ni = 0; ni < 4; ni++)
#pragma unroll
            for (int mi = 0; mi < 2; mi++)
                mma_f16(acc[mi][ni], ah[mi], bh[ni]);
#pragma unroll
        for (int ni = 0; ni < 4; ni++)
#pragma unroll
            for (int mi = 0; mi < 2; mi++)
                mma_f16(acc[mi][ni], ah[mi], bl_[ni]);
#pragma unroll
        for (int ni = 0; ni < 4; ni++)
#pragma unroll
            for (int mi = 0; mi < 2; mi++)
                mma_f16(acc[mi][ni], al_[mi], bh[ni]);
    }

#pragma unroll
    for (int mi = 0; mi < 2; mi++) {
        const int row = mbase + wm + mi * 16 + lrow;
#pragma unroll
        for (int ni = 0; ni < 4; ni++) {
            const int col = nbase + wn + ni * 8 + lcol * 2;
            if (row < R_ROWS)
                *(float2*)&Cb[(size_t)row * T_LEN + col] =
                    make_float2(acc[mi][ni][0], acc[mi][ni][1]);
            if (row + 8 < R_ROWS)
                *(float2*)&Cb[(size_t)(row + 8) * T_LEN + col] =
                    make_float2(acc[mi][ni][2], acc[mi][ni][3]);
        }
    }
}

// ============================================================
// Softmax over t for 4 synonym rows -> combined mean weights
// ============================================================
__global__ void __launch_bounds__(128) softmax_combine_kernel(
    const float* __restrict__ scores, float* __restrict__ w)
{
    __shared__ float ex[4][1024];
    __shared__ float invl[4];
    const int blk = blockIdx.x;
    const int bz = blk / C_CLS, c = blk % C_CLS;
    const int warp = threadIdx.x >> 5, lane = threadIdx.x & 31;

    const float* row = scores + ((size_t)bz * R_ROWS + c * 4 + warp) * T_LEN;

    float m = -INFINITY;
    for (int t = lane; t < T_LEN; t += 32) m = fmaxf(m, row[t]);
#pragma unroll
    for (int o = 16; o > 0; o >>= 1) m = fmaxf(m, __shfl_xor_sync(0xffffffffu, m, o));

    float ssum = 0.f;
    for (int t = lane; t < T_LEN; t += 32) {
        float e = expf(row[t] - m);
        ex[warp][t] = e;
        ssum += e;
    }
#pragma unroll
    for (int o = 16; o > 0; o >>= 1) ssum += __shfl_xor_sync(0xffffffffu, ssum, o);
    if (lane == 0) invl[warp] = 0.25f / ssum;
    __syncthreads();

    float* wr = w + ((size_t)bz * C_CLS + c) * T_LEN;
    for (int t = threadIdx.x; t < T_LEN; t += 128)
        wr[t] = ex[0][t] * invl[0] + ex[1][t] * invl[1]
              + ex[2][t] * invl[2] + ex[3][t] * invl[3];
}

// ============================================================
// Fused m2 + final (smem pad 68 = 272B stride, 16B multiple)
// ============================================================
__global__ void __launch_bounds__(256) m2_fused_kernel(
    const float* __restrict__ H, const float* __restrict__ wql,
    const float* __restrict__ w, float* __restrict__ out)
{
    const int bz = blockIdx.z;
    const int b = bz / NH, z = bz % NH;
    const int tbase = blockIdx.y * 64;

    __shared__ float Qs[64][68];
    __shared__ float Ks[64][68];

    const int tid = threadIdx.x;

#pragma unroll
    for (int i = 0; i < 4; i++) {
        int fl = tid + 256 * i;
        int row = fl >> 4;
        int hc = (fl & 15) * 4;
        float4 v = *(const float4*)&H[(size_t)(b * T_LEN + tbase + row) * D_MODEL + z * HDIM + hc];
        Qs[hc + 0][row] = tanhf(v.x); Qs[hc + 1][row] = tanhf(v.y);
        Qs[hc + 2][row] = tanhf(v.z); Qs[hc + 3][row] = tanhf(v.w);
    }
#pragma unroll
    for (int i = 0; i < 4; i++) {
        int fl = tid + 256 * i;
        int row = fl >> 4;
        int hc = (fl & 15) * 4;
        float4 v = make_float4(0.f, 0.f, 0.f, 0.f);
        if (row < C_CLS)
            v = *(const float4*)&wql[(size_t)row * D_MODEL + z * HDIM + hc];
        Ks[hc + 0][row] = v.x; Ks[hc + 1][row] = v.y;
        Ks[hc + 2][row] = v.z; Ks[hc + 3][row] = v.w;
    }
    __syncthreads();

    const int tx = tid & 15, ty = tid >> 4;
    float acc[4][4];
#pragma unroll
    for (int i = 0; i < 4; i++)
#pragma unroll
        for (int j = 0; j < 4; j++) acc[i][j] = 0.f;

#pragma unroll
    for (int h = 0; h < 64; h++) {
        float ar[4], br[4];
        *(float4*)&ar[0] = *(float4*)&Qs[h][ty * 4];
        *(float4*)&br[0] = *(float4*)&Ks[h][tx * 4];
#pragma unroll
        for (int i = 0; i < 4; i++)
#pragma unroll
            for (int j = 0; j < 4; j++)
                acc[i][j] = fmaf(ar[i], br[j], acc[i][j]);
    }
    __syncthreads();

    float* pm = &Qs[0][0];
    float p[4];
#pragma unroll
    for (int j = 0; j < 4; j++) {
        const int c = tx * 4 + j;
        p[j] = 0.f;
        if (c < C_CLS) {
            float4 wv = *(const float4*)&w[((size_t)bz * C_CLS + c) * T_LEN + tbase + ty * 4];
            p[j] = acc[0][j] * wv.x + acc[1][j] * wv.y
                 + acc[2][j] * wv.z + acc[3][j] * wv.w;
        }
        pm[ty * 64 + tx * 4 + j] = p[j];
    }
    __syncthreads();

    if (tid < 64 && tid < C_CLS) {
        float s = 0.f;
#pragma unroll
        for (int r = 0; r < 16; r++) s += pm[r * 64 + tid];
        atomicAdd(&out[b * C_CLS + tid], s);
    }
}

// ============================================================
extern "C" void kernel_launch(void* const* d_in, const int* in_sizes, int n_in,
                              void* d_out, int out_size)
{
    const float* Q   = (const float*)d_in[0];
    const float* H   = (const float*)d_in[1];
    const float* ql  = (const float*)d_in[2];
    const float* WQw = (const float*)d_in[3];
    const float* WQb = (const float*)d_in[4];
    const float* WKw = (const float*)d_in[5];
    const float* WKb = (const float*)d_in[6];
    const float* WVw = (const float*)d_in[7];
    const float* WVb = (const float*)d_in[8];
    float* out = (float*)d_out;

    __half* pool;
    float *wql, *scores, *w;
    cudaGetSymbolAddress((void**)&pool,   g_hf);
    cudaGetSymbolAddress((void**)&wql,    g_wql);
    cudaGetSymbolAddress((void**)&scores, g_scores);
    cudaGetSymbolAddress((void**)&w,      g_w);

    cudaFuncSetAttribute(proj_f16_kernel,
                         cudaFuncAttributeMaxDynamicSharedMemorySize, PROJ_SMEM);
    cudaFuncSetAttribute(scores_f16_kernel,
                         cudaFuncAttributeMaxDynamicSharedMemorySize, SC_SMEM_B);

    // pre-split fp32 -> fp16 hi/lo (also zeroes out)
    split_all_kernel<<<(N_H + N_Q + N_QL + 255) / 256, 256>>>(H, Q, ql, pool, out);
    split_transpose_kernel<<<dim3(24, 24, 3), 256>>>(WKw, WQw, WVw, pool);

    // fused projections (single-barrier pipelined, 3 blocks/SM)
    proj_f16_kernel<<<dim3(12, 32, 3), 256, PROJ_SMEM>>>(pool, pool, WKb, WQb, WVb, wql);

    // scores per (b,z): cp.async loads + fp16x3 mma (f32 acc, 4 blocks/SM)
    scores_f16_kernel<<<dim3(8, 4, BZ), 256, SC_SMEM_B>>>(pool, scores);

    softmax_combine_kernel<<<BZ * C_CLS, 128>>>(scores, w);

    m2_fused_kernel<<<dim3(1, 16, BZ), 256>>>(H, wql, w, out);
}